// round 4
// baseline (speedup 1.0000x reference)
#include <cuda_runtime.h>

// SPDUnVectorize: out[b,i,j] = x[b, tri(min(i,j), max(i,j))]
// tri(i,j), i<=j: i*N - i*(i-1)/2 + (j-i)
//
// Tiled symmetric expansion, scalar lane-per-column mapping:
//  - one CTA per 64x64 tile of the upper block-triangle (10 tiles/batch)
//  - off-diagonal: read packed tile once (coalesced), write it out directly,
//    stage in smem, write transpose. Lane = column -> conflict-free smem in
//    BOTH directions (store s[r][c] row-major, read s[c][rr] column-major:
//    banks (c + rr) mod 32 all distinct for 32 consecutive c).
//  - diagonal: load upper half, mirror through smem.
//  - __stcs streaming stores (output is write-once), high occupancy target.

#define NMAT 256
#define DTRI (NMAT * (NMAT + 1) / 2)   // 32896
#define TB 64
#define NTB (NMAT / TB)                 // 4
#define NTILES (NTB * (NTB + 1) / 2)    // 10
#define THREADS 256

__constant__ int c_tbi[NTILES] = {0,0,0,0,1,1,1,2,2,3};
__constant__ int c_tbj[NTILES] = {0,1,2,3,1,2,3,2,3,3};

__global__ void __launch_bounds__(THREADS, 8)
spd_unvec_tiled(const float* __restrict__ x, float* __restrict__ out) {
    __shared__ float s[TB][TB + 1];

    const int t    = threadIdx.x;
    const int b    = blockIdx.y;
    const int tile = blockIdx.x;
    const int bi = c_tbi[tile];
    const int bj = c_tbj[tile];

    const float* __restrict__ xr = x + (size_t)b * DTRI;
    float* __restrict__ o = out + (size_t)b * (NMAT * NMAT);

    const int c  = t & 63;    // column within tile (lane-consecutive)
    const int r0 = t >> 6;    // 0..3

    if (bi != bj) {
        // ---- phase 1: load packed tile, stage in smem, write upper tile ----
        #pragma unroll
        for (int k = 0; k < 16; k++) {
            const int r = r0 + (k << 2);
            const int i = bi * TB + r;
            const int idx = i * NMAT - (i * (i - 1)) / 2 - i + bj * TB + c;
            const float v = __ldg(xr + idx);
            s[r][c] = v;
            __stcs(o + i * NMAT + bj * TB + c, v);
        }
        __syncthreads();

        // ---- phase 2: write transposed tile to out[bj, bi] ----
        #pragma unroll
        for (int k = 0; k < 16; k++) {
            const int rr = r0 + (k << 2);
            const int j  = bj * TB + rr;
            __stcs(o + j * NMAT + bi * TB + c, s[c][rr]);
        }
    } else {
        // ---- diagonal tile: load upper part (c >= r), mirror lower ----
        #pragma unroll
        for (int k = 0; k < 16; k++) {
            const int r = r0 + (k << 2);
            const int i = bi * TB + r;
            if (c >= r) {
                const int idx = i * NMAT - (i * (i - 1)) / 2 - i + bi * TB + c;
                s[r][c] = __ldg(xr + idx);
            }
        }
        __syncthreads();

        #pragma unroll
        for (int k = 0; k < 16; k++) {
            const int r = r0 + (k << 2);
            const int i = bi * TB + r;
            const float v = (c >= r) ? s[r][c] : s[c][r];
            __stcs(o + i * NMAT + bi * TB + c, v);
        }
    }
}

extern "C" void kernel_launch(void* const* d_in, const int* in_sizes, int n_in,
                              void* d_out, int out_size) {
    const float* x = (const float*)d_in[0];
    float* out = (float*)d_out;

    const int B = out_size / (NMAT * NMAT);   // 4096

    dim3 grid(NTILES, B);
    spd_unvec_tiled<<<grid, THREADS>>>(x, out);
}

// round 5
// speedup vs baseline: 1.0018x; 1.0018x over previous
#include <cuda_runtime.h>

// SPDUnVectorize: out[b,i,j] = x[b, tri(min(i,j), max(i,j))]
// tri(i,j), i<=j: i*N - i*(i-1)/2 + (j-i)
//
// Tiled symmetric expansion, scalar lane-per-column mapping:
//  - one CTA per 64x64 tile of the upper block-triangle (10 tiles/batch)
//  - off-diagonal: read packed tile once (coalesced), write it out directly,
//    stage in smem, write transpose. Lane = column -> conflict-free smem in
//    BOTH directions (store s[r][c] row-major, read s[c][rr] column-major:
//    banks (c + rr) mod 32 all distinct for 32 consecutive c).
//  - diagonal: load upper half, mirror through smem.
//  - __stcs streaming stores (output is write-once), high occupancy target.

#define NMAT 256
#define DTRI (NMAT * (NMAT + 1) / 2)   // 32896
#define TB 64
#define NTB (NMAT / TB)                 // 4
#define NTILES (NTB * (NTB + 1) / 2)    // 10
#define THREADS 256

__constant__ int c_tbi[NTILES] = {0,0,0,0,1,1,1,2,2,3};
__constant__ int c_tbj[NTILES] = {0,1,2,3,1,2,3,2,3,3};

__global__ void __launch_bounds__(THREADS, 8)
spd_unvec_tiled(const float* __restrict__ x, float* __restrict__ out) {
    __shared__ float s[TB][TB + 1];

    const int t    = threadIdx.x;
    const int b    = blockIdx.y;
    const int tile = blockIdx.x;
    const int bi = c_tbi[tile];
    const int bj = c_tbj[tile];

    const float* __restrict__ xr = x + (size_t)b * DTRI;
    float* __restrict__ o = out + (size_t)b * (NMAT * NMAT);

    const int c  = t & 63;    // column within tile (lane-consecutive)
    const int r0 = t >> 6;    // 0..3

    if (bi != bj) {
        // ---- phase 1: load packed tile, stage in smem, write upper tile ----
        #pragma unroll
        for (int k = 0; k < 16; k++) {
            const int r = r0 + (k << 2);
            const int i = bi * TB + r;
            const int idx = i * NMAT - (i * (i - 1)) / 2 - i + bj * TB + c;
            const float v = __ldg(xr + idx);
            s[r][c] = v;
            __stcs(o + i * NMAT + bj * TB + c, v);
        }
        __syncthreads();

        // ---- phase 2: write transposed tile to out[bj, bi] ----
        #pragma unroll
        for (int k = 0; k < 16; k++) {
            const int rr = r0 + (k << 2);
            const int j  = bj * TB + rr;
            __stcs(o + j * NMAT + bi * TB + c, s[c][rr]);
        }
    } else {
        // ---- diagonal tile: load upper part (c >= r), mirror lower ----
        #pragma unroll
        for (int k = 0; k < 16; k++) {
            const int r = r0 + (k << 2);
            const int i = bi * TB + r;
            if (c >= r) {
                const int idx = i * NMAT - (i * (i - 1)) / 2 - i + bi * TB + c;
                s[r][c] = __ldg(xr + idx);
            }
        }
        __syncthreads();

        #pragma unroll
        for (int k = 0; k < 16; k++) {
            const int r = r0 + (k << 2);
            const int i = bi * TB + r;
            const float v = (c >= r) ? s[r][c] : s[c][r];
            __stcs(o + i * NMAT + bi * TB + c, v);
        }
    }
}

extern "C" void kernel_launch(void* const* d_in, const int* in_sizes, int n_in,
                              void* d_out, int out_size) {
    const float* x = (const float*)d_in[0];
    float* out = (float*)d_out;

    const int B = out_size / (NMAT * NMAT);   // 4096

    dim3 grid(NTILES, B);
    spd_unvec_tiled<<<grid, THREADS>>>(x, out);
}

// round 6
// speedup vs baseline: 1.0023x; 1.0005x over previous
#include <cuda_runtime.h>

// SPDUnVectorize: out[b,i,j] = x[b, tri(min(i,j), max(i,j))]
// tri(i,j), i<=j: i*N - i*(i-1)/2 + (j-i)
//
// Tiled symmetric expansion, scalar lane-per-column mapping:
//  - one CTA per 64x64 tile of the upper block-triangle (10 tiles/batch)
//  - off-diagonal: read packed tile once (coalesced), write it out directly,
//    stage in smem, write transpose. Lane = column -> conflict-free smem in
//    BOTH directions (store s[r][c] row-major, read s[c][rr] column-major:
//    banks (c + rr) mod 32 all distinct for 32 consecutive c).
//  - diagonal: load upper half, mirror through smem.
//  - __stcs streaming stores (output is write-once), high occupancy target.

#define NMAT 256
#define DTRI (NMAT * (NMAT + 1) / 2)   // 32896
#define TB 64
#define NTB (NMAT / TB)                 // 4
#define NTILES (NTB * (NTB + 1) / 2)    // 10
#define THREADS 256

__constant__ int c_tbi[NTILES] = {0,0,0,0,1,1,1,2,2,3};
__constant__ int c_tbj[NTILES] = {0,1,2,3,1,2,3,2,3,3};

__global__ void __launch_bounds__(THREADS, 8)
spd_unvec_tiled(const float* __restrict__ x, float* __restrict__ out) {
    __shared__ float s[TB][TB + 1];

    const int t    = threadIdx.x;
    const int b    = blockIdx.y;
    const int tile = blockIdx.x;
    const int bi = c_tbi[tile];
    const int bj = c_tbj[tile];

    const float* __restrict__ xr = x + (size_t)b * DTRI;
    float* __restrict__ o = out + (size_t)b * (NMAT * NMAT);

    const int c  = t & 63;    // column within tile (lane-consecutive)
    const int r0 = t >> 6;    // 0..3

    if (bi != bj) {
        // ---- phase 1: load packed tile, stage in smem, write upper tile ----
        #pragma unroll
        for (int k = 0; k < 16; k++) {
            const int r = r0 + (k << 2);
            const int i = bi * TB + r;
            const int idx = i * NMAT - (i * (i - 1)) / 2 - i + bj * TB + c;
            const float v = __ldg(xr + idx);
            s[r][c] = v;
            __stcs(o + i * NMAT + bj * TB + c, v);
        }
        __syncthreads();

        // ---- phase 2: write transposed tile to out[bj, bi] ----
        #pragma unroll
        for (int k = 0; k < 16; k++) {
            const int rr = r0 + (k << 2);
            const int j  = bj * TB + rr;
            __stcs(o + j * NMAT + bi * TB + c, s[c][rr]);
        }
    } else {
        // ---- diagonal tile: load upper part (c >= r), mirror lower ----
        #pragma unroll
        for (int k = 0; k < 16; k++) {
            const int r = r0 + (k << 2);
            const int i = bi * TB + r;
            if (c >= r) {
                const int idx = i * NMAT - (i * (i - 1)) / 2 - i + bi * TB + c;
                s[r][c] = __ldg(xr + idx);
            }
        }
        __syncthreads();

        #pragma unroll
        for (int k = 0; k < 16; k++) {
            const int r = r0 + (k << 2);
            const int i = bi * TB + r;
            const float v = (c >= r) ? s[r][c] : s[c][r];
            __stcs(o + i * NMAT + bi * TB + c, v);
        }
    }
}

extern "C" void kernel_launch(void* const* d_in, const int* in_sizes, int n_in,
                              void* d_out, int out_size) {
    const float* x = (const float*)d_in[0];
    float* out = (float*)d_out;

    const int B = out_size / (NMAT * NMAT);   // 4096

    dim3 grid(NTILES, B);
    spd_unvec_tiled<<<grid, THREADS>>>(x, out);
}